// round 1
// baseline (speedup 1.0000x reference)
#include <cuda_runtime.h>

#define N_WIRES 12
#define N_LAYERS 3
#define DIM 4096
#define BATCH 512
#define NT 256
#define AMPS_PER_THREAD (DIM / NT)       // 16
#define PAIRS_PER_THREAD (DIM / 2 / NT)  // 8

__global__ __launch_bounds__(NT)
void qsim_kernel(const float* __restrict__ state,
                 const float* __restrict__ weights,
                 const float* __restrict__ head_w,
                 const float* __restrict__ head_b,
                 float* __restrict__ out)
{
    __shared__ float sre[DIM];
    __shared__ float sim[DIM];
    __shared__ float U[N_LAYERS * N_WIRES][8];  // r00,i00,r01,i01,r10,i10,r11,i11
    __shared__ float hw[N_WIRES];
    __shared__ float warpsum[NT / 32];

    const int tid = threadIdx.x;
    const int b = blockIdx.x;

    // ---- per-block gate matrix computation: U = RZ(c) RY(b) RX(a) ----
    if (tid < N_LAYERS * N_WIRES) {
        float a = weights[tid * 3 + 0];
        float bb = weights[tid * 3 + 1];
        float c = weights[tid * 3 + 2];
        float sa, ca, sb, cb, sc, cc;
        sincosf(0.5f * a, &sa, &ca);
        sincosf(0.5f * bb, &sb, &cb);
        sincosf(0.5f * c, &sc, &cc);
        // M = RY @ RX
        float m00r = cb * ca, m00i = sb * sa;
        float m01r = -sb * ca, m01i = -cb * sa;
        float m10r = sb * ca, m10i = -cb * sa;
        float m11r = cb * ca, m11i = -sb * sa;
        // U row0 = e^{-ic/2} * M row0 ; U row1 = e^{+ic/2} * M row1
        U[tid][0] = m00r * cc + m00i * sc;
        U[tid][1] = m00i * cc - m00r * sc;
        U[tid][2] = m01r * cc + m01i * sc;
        U[tid][3] = m01i * cc - m01r * sc;
        U[tid][4] = m10r * cc - m10i * sc;
        U[tid][5] = m10i * cc + m10r * sc;
        U[tid][6] = m11r * cc - m11i * sc;
        U[tid][7] = m11i * cc + m11r * sc;
    }
    if (tid < N_WIRES) hw[tid] = head_w[tid];

    // ---- load state (real input, zero imaginary) ----
    const float* st = state + (size_t)b * DIM;
#pragma unroll
    for (int k = 0; k < AMPS_PER_THREAD; k++) {
        int i = tid + k * NT;
        sre[i] = st[i];
        sim[i] = 0.0f;
    }
    __syncthreads();

    // ---- circuit ----
    for (int l = 0; l < N_LAYERS; l++) {
        for (int w = 0; w < N_WIRES; w++) {
            const float* u = U[l * N_WIRES + w];
            float u00r = u[0], u00i = u[1], u01r = u[2], u01i = u[3];
            float u10r = u[4], u10i = u[5], u11r = u[6], u11i = u[7];
            int bp = (N_WIRES - 1) - w;  // wire 0 = MSB
            int dr = 1 << bp;
#pragma unroll
            for (int k = 0; k < PAIRS_PER_THREAD; k++) {
                int p = tid + k * NT;
                int low = p & (dr - 1);
                int i0 = ((p >> bp) << (bp + 1)) | low;
                int i1 = i0 + dr;
                float r0 = sre[i0], q0 = sim[i0];
                float r1 = sre[i1], q1 = sim[i1];
                float nr0 = u00r * r0 - u00i * q0 + u01r * r1 - u01i * q1;
                float ni0 = u00r * q0 + u00i * r0 + u01r * q1 + u01i * r1;
                float nr1 = u10r * r0 - u10i * q0 + u11r * r1 - u11i * q1;
                float ni1 = u10r * q0 + u10i * r0 + u11r * q1 + u11i * r1;
                sre[i0] = nr0; sim[i0] = ni0;
                sre[i1] = nr1; sim[i1] = ni1;
            }
            __syncthreads();
        }
        // ---- fused CNOT chain: psi_new[y] = psi_old[y ^ (y >> 1)] ----
        float tr[AMPS_PER_THREAD], ti[AMPS_PER_THREAD];
#pragma unroll
        for (int k = 0; k < AMPS_PER_THREAD; k++) {
            int y = tid + k * NT;
            int src = y ^ (y >> 1);
            tr[k] = sre[src];
            ti[k] = sim[src];
        }
        __syncthreads();
#pragma unroll
        for (int k = 0; k < AMPS_PER_THREAD; k++) {
            int y = tid + k * NT;
            sre[y] = tr[k];
            sim[y] = ti[k];
        }
        __syncthreads();
    }

    // ---- fused <Z_w> + linear head: out = sum_i |psi_i|^2 * c_i + bias ----
    float acc = 0.0f;
#pragma unroll
    for (int k = 0; k < AMPS_PER_THREAD; k++) {
        int i = tid + k * NT;
        float pr = sre[i] * sre[i] + sim[i] * sim[i];
        float c = 0.0f;
#pragma unroll
        for (int w = 0; w < N_WIRES; w++) {
            c += ((i >> ((N_WIRES - 1) - w)) & 1) ? -hw[w] : hw[w];
        }
        acc += pr * c;
    }
#pragma unroll
    for (int o = 16; o > 0; o >>= 1)
        acc += __shfl_xor_sync(0xffffffffu, acc, o);
    if ((tid & 31) == 0) warpsum[tid >> 5] = acc;
    __syncthreads();
    if (tid == 0) {
        float s = 0.0f;
#pragma unroll
        for (int i = 0; i < NT / 32; i++) s += warpsum[i];
        out[b] = s + head_b[0];
    }
}

extern "C" void kernel_launch(void* const* d_in, const int* in_sizes, int n_in,
                              void* d_out, int out_size)
{
    const float* state = (const float*)d_in[0];    // (512, 4096)
    const float* weights = (const float*)d_in[1];  // (3, 12, 3)
    const float* head_w = (const float*)d_in[2];   // (1, 12)
    const float* head_b = (const float*)d_in[3];   // (1,)
    float* out = (float*)d_out;                    // (512,)
    qsim_kernel<<<BATCH, NT>>>(state, weights, head_w, head_b, out);
}

// round 2
// speedup vs baseline: 1.9284x; 1.9284x over previous
#include <cuda_runtime.h>

#define NW 12
#define NL 3
#define DIM 4096
#define NT 256

// padded float2 index: insert one float2 pad every 16 -> conflict-free remaps
__device__ __forceinline__ int pidx(int i) { return i + (i >> 4); }

// Apply 4 register-local gates. Local bit j corresponds to wire (wbase - j).
__device__ __forceinline__ void apply_group(float ar[16], float ai[16],
                                            const float4 (*__restrict__ Usm)[2],
                                            int base_gate, int wbase)
{
#pragma unroll
    for (int j = 0; j < 4; j++) {
        float4 ua = Usm[base_gate + (wbase - j)][0]; // u00r,u00i,u01r,u01i
        float4 ub = Usm[base_gate + (wbase - j)][1]; // u10r,u10i,u11r,u11i
#pragma unroll
        for (int p = 0; p < 8; p++) {
            int k0 = ((p >> j) << (j + 1)) | (p & ((1 << j) - 1));
            int k1 = k0 | (1 << j);
            float r0 = ar[k0], q0 = ai[k0];
            float r1 = ar[k1], q1 = ai[k1];
            ar[k0] = ua.x * r0 - ua.y * q0 + ua.z * r1 - ua.w * q1;
            ai[k0] = ua.x * q0 + ua.y * r0 + ua.z * q1 + ua.w * r1;
            ar[k1] = ub.x * r0 - ub.y * q0 + ub.z * r1 - ub.w * q1;
            ai[k1] = ub.x * q0 + ub.y * r0 + ub.z * q1 + ub.w * r1;
        }
    }
}

__global__ __launch_bounds__(NT, 4)
void qsim_kernel(const float* __restrict__ state,
                 const float* __restrict__ weights,
                 const float* __restrict__ head_w,
                 const float* __restrict__ head_b,
                 float* __restrict__ out)
{
    __shared__ float2 buf[DIM + DIM / 16];  // 4352 float2 = 34,816 B
    __shared__ float4 Usm[NL * NW][2];
    __shared__ float hw[NW];
    __shared__ float warpsum[NT / 32];

    const int tid = threadIdx.x;
    const int b = blockIdx.x;

    // ---- gate matrices U = RZ(c) RY(b) RX(a) ----
    if (tid < NL * NW) {
        float a = weights[tid * 3 + 0];
        float bb = weights[tid * 3 + 1];
        float c = weights[tid * 3 + 2];
        float sa, ca, sb, cb, sc, cc;
        sincosf(0.5f * a, &sa, &ca);
        sincosf(0.5f * bb, &sb, &cb);
        sincosf(0.5f * c, &sc, &cc);
        float m00r = cb * ca, m00i = sb * sa;
        float m01r = -sb * ca, m01i = -cb * sa;
        float m10r = sb * ca, m10i = -cb * sa;
        float m11r = cb * ca, m11i = -sb * sa;
        float4 ua, ub;
        ua.x = m00r * cc + m00i * sc;  ua.y = m00i * cc - m00r * sc;
        ua.z = m01r * cc + m01i * sc;  ua.w = m01i * cc - m01r * sc;
        ub.x = m10r * cc - m10i * sc;  ub.y = m10i * cc + m10r * sc;
        ub.z = m11r * cc - m11i * sc;  ub.w = m11i * cc + m11r * sc;
        Usm[tid][0] = ua;
        Usm[tid][1] = ub;
    }
    if (tid < NW) hw[tid] = head_w[tid];

    // ---- load state directly to registers (mapping A: i = (t<<4)|k) ----
    float ar[16], ai[16];
    const float4* st4 = (const float4*)(state + (size_t)b * DIM);
#pragma unroll
    for (int q = 0; q < 4; q++) {
        float4 v = st4[tid * 4 + q];
        ar[q * 4 + 0] = v.x; ar[q * 4 + 1] = v.y;
        ar[q * 4 + 2] = v.z; ar[q * 4 + 3] = v.w;
        ai[q * 4 + 0] = 0.f; ai[q * 4 + 1] = 0.f;
        ai[q * 4 + 2] = 0.f; ai[q * 4 + 3] = 0.f;
    }
    __syncthreads();  // Usm / hw ready

    for (int l = 0; l < NL; l++) {
        const int bg = l * NW;

        // group A: bits 0-3 local -> wires 11..8
        apply_group(ar, ai, Usm, bg, 11);

        // remap A -> B
        __syncthreads();
#pragma unroll
        for (int k = 0; k < 16; k++) {
            int i = (tid << 4) | k;
            buf[pidx(i)] = make_float2(ar[k], ai[k]);
        }
        __syncthreads();
#pragma unroll
        for (int k = 0; k < 16; k++) {
            int i = ((tid >> 4) << 8) | (k << 4) | (tid & 15);
            float2 v = buf[pidx(i)];
            ar[k] = v.x; ai[k] = v.y;
        }

        // group B: bits 4-7 local -> wires 7..4
        apply_group(ar, ai, Usm, bg, 7);

        // remap B -> C
        __syncthreads();
#pragma unroll
        for (int k = 0; k < 16; k++) {
            int i = ((tid >> 4) << 8) | (k << 4) | (tid & 15);
            buf[pidx(i)] = make_float2(ar[k], ai[k]);
        }
        __syncthreads();
#pragma unroll
        for (int k = 0; k < 16; k++) {
            int i = (k << 8) | tid;
            float2 v = buf[pidx(i)];
            ar[k] = v.x; ai[k] = v.y;
        }

        // group C: bits 8-11 local -> wires 3..0
        apply_group(ar, ai, Usm, bg, 3);

        // layer boundary: remap C -> A with fused CNOT-chain permutation
        // psi_new[y] = psi_old[y ^ (y>>1)]
        if (l < NL - 1) {
            __syncthreads();
#pragma unroll
            for (int k = 0; k < 16; k++) {
                int i = (k << 8) | tid;
                buf[pidx(i)] = make_float2(ar[k], ai[k]);
            }
            __syncthreads();
#pragma unroll
            for (int k = 0; k < 16; k++) {
                int y = (tid << 4) | k;
                int src = y ^ (y >> 1);
                float2 v = buf[pidx(src)];
                ar[k] = v.x; ai[k] = v.y;
            }
        }
    }

    // ---- measurement from mapping C regs, last CNOT perm folded into weights.
    // out = sum_x |psi[x]|^2 * c(prefixXOR(x)) + bias
    // x = (k<<8)|t ; y = pxor(x): y[8..11]=pxor4(k), y[0..7]=pxor8(t) ^ (par(k)?0xFF:0)
    int m8 = tid;
    m8 ^= m8 >> 1; m8 ^= m8 >> 2; m8 ^= m8 >> 4;  // suffix-XOR over 8 bits
    // wires 4..11 <-> y bits 7..0
    float c_low = 0.f;
#pragma unroll
    for (int w = 4; w < 12; w++) {
        c_low += ((m8 >> (11 - w)) & 1) ? -hw[w] : hw[w];
    }
    float acc = 0.f;
#pragma unroll
    for (int k = 0; k < 16; k++) {
        int g4 = k;
        g4 ^= g4 >> 1; g4 ^= g4 >> 2;  // suffix-XOR over 4 bits
        float c_high = 0.f;
#pragma unroll
        for (int w = 0; w < 4; w++) {
            c_high += ((g4 >> (3 - w)) & 1) ? -hw[w] : hw[w];
        }
        float c = c_high + ((g4 & 1) ? -c_low : c_low);  // par(k) = LSB of suffix-XOR
        acc += (ar[k] * ar[k] + ai[k] * ai[k]) * c;
    }
#pragma unroll
    for (int o = 16; o > 0; o >>= 1)
        acc += __shfl_xor_sync(0xffffffffu, acc, o);
    if ((tid & 31) == 0) warpsum[tid >> 5] = acc;
    __syncthreads();
    if (tid == 0) {
        float s = 0.f;
#pragma unroll
        for (int i = 0; i < NT / 32; i++) s += warpsum[i];
        out[b] = s + head_b[0];
    }
}

extern "C" void kernel_launch(void* const* d_in, const int* in_sizes, int n_in,
                              void* d_out, int out_size)
{
    const float* state   = (const float*)d_in[0];  // (512, 4096)
    const float* weights = (const float*)d_in[1];  // (3, 12, 3)
    const float* head_w  = (const float*)d_in[2];  // (1, 12)
    const float* head_b  = (const float*)d_in[3];  // (1,)
    float* out = (float*)d_out;                    // (512,)
    qsim_kernel<<<512, NT>>>(state, weights, head_w, head_b, out);
}